// round 2
// baseline (speedup 1.0000x reference)
#include <cuda_runtime.h>
#include <math.h>

#define BSZ     64
#define NF      16
#define NFILT   32          // 2*NF
#define KTAP    8
#define LSEQ    16384
#define THRV    0.25f
#define BETA    15.0f
#define TCH     128         // chunk length (was 512)
#define WUP     64          // warm-up steps: alpha^64 ~ 5e-10, sub-tolerance
#define NCHUNK  (LSEQ / TCH)

// one warp per (b, chunk); lane = filter index 0..31
__global__ __launch_bounds__(128, 8)
void snn_scan_kernel(const float* __restrict__ x,
                     const float* __restrict__ wa,
                     const float* __restrict__ wb,
                     const float* __restrict__ ta,
                     const float* __restrict__ tb,
                     float* __restrict__ out)
{
    const int warp_global = (blockIdx.x * blockDim.x + threadIdx.x) >> 5;
    const int lane = threadIdx.x & 31;
    if (warp_global >= BSZ * NCHUNK) return;

    const int b     = warp_global / NCHUNK;
    const int chunk = warp_global % NCHUNK;
    const int f     = lane;
    const int ch    = f >> 4;            // 0: stream a, 1: stream b

    // ---- per-filter constants ----
    const float* wsrc = (ch == 0) ? (wa + f * KTAP) : (wb + (f - NF) * KTAP);
    float w[KTAP];
    float ss = 0.f;
    #pragma unroll
    for (int k = 0; k < KTAP; k++) { w[k] = wsrc[k]; ss = __fmaf_rn(w[k], w[k], ss); }
    const float inv = 1.0f / fmaxf(sqrtf(ss), 1e-8f);
    #pragma unroll
    for (int k = 0; k < KTAP; k++) w[k] = __fmul_rn(w[k], inv);

    const float raw   = (ch == 0) ? ta[f] : tb[f - NF];
    const float sp    = fmaxf(raw, 0.f) + log1pf(expf(-fabsf(raw)));   // softplus
    const float tau   = sp + 1e-4f;
    const float alpha = expf(-1.0f / tau);
    const float oma   = 1.0f - alpha;

    const float* xb = x + (size_t)(b * 2 + ch) * LSEQ;

    const int t0   = chunk * TCH;
    const int wlen = (chunk == 0) ? 0 : WUP;
    const int ts   = t0 - wlen;

    // ---- conv history window: hist[i] = x[tcur-8+i] ----
    float hist[8];
    if (chunk == 0) {
        #pragma unroll
        for (int k = 0; k < 8; k++) hist[k] = 0.f;   // causal left pad
    } else {
        const float4 h0 = *(const float4*)(xb + ts - 8);
        const float4 h1 = *(const float4*)(xb + ts - 4);
        hist[0]=h0.x; hist[1]=h0.y; hist[2]=h0.z; hist[3]=h0.w;
        hist[4]=h1.x; hist[5]=h1.y; hist[6]=h1.z; hist[7]=h1.w;
    }

    // ---- recurrence state in vp-form ----
    // vp_{t} = spike_{t-1} ? d_t : fma(alpha, vp_{t-1}, d_t),  d = (1-alpha)*I
    // (exact: when spike, v=0 and alpha*0+d == d bit-exactly)
    float vp = 0.f;
    bool  spike = false;

    // ---- phase 1: warm-up (no outputs), contraction kills v(0) error ----
    for (int g = 0; g < wlen; g += 4) {
        const float4 c4 = *(const float4*)(xb + ts + g);
        float c[12];
        #pragma unroll
        for (int k = 0; k < 8; k++) c[k] = hist[k];
        c[8]=c4.x; c[9]=c4.y; c[10]=c4.z; c[11]=c4.w;
        float d[4];
        #pragma unroll
        for (int j = 0; j < 4; j++) {
            float I = 0.f;
            #pragma unroll
            for (int k = 0; k < 8; k++) I = __fmaf_rn(w[k], c[j + 1 + k], I);
            d[j] = __fmul_rn(oma, I);
        }
        #pragma unroll
        for (int j = 0; j < 4; j++) {
            const float fmares = __fmaf_rn(alpha, vp, d[j]);
            vp    = spike ? d[j] : fmares;
            spike = (vp >= THRV);
        }
        #pragma unroll
        for (int k = 0; k < 8; k++) hist[k] = c[k + 4];
    }

    // ---- output pointers ----
    const size_t plane = (size_t)BSZ * NFILT * LSEQ;
    const size_t base  = (size_t)(b * NFILT + f) * LSEQ + t0;
    float* __restrict__ vout = out + base;
    float* __restrict__ zout = out + plane + base;
    float* __restrict__ souT = out + 2 * plane + base;
    float* __restrict__ lout = out + 3 * plane + (size_t)b * LSEQ + t0;

    // ---- phase 2: main scan with outputs ----
    for (int g = 0; g < TCH; g += 4) {
        const float4 c4 = *(const float4*)(xb + t0 + g);
        float c[12];
        #pragma unroll
        for (int k = 0; k < 8; k++) c[k] = hist[k];
        c[8]=c4.x; c[9]=c4.y; c[10]=c4.z; c[11]=c4.w;

        // conv currents off the critical path
        float d[4];
        #pragma unroll
        for (int j = 0; j < 4; j++) {
            float I = 0.f;
            #pragma unroll
            for (int k = 0; k < 8; k++) I = __fmaf_rn(w[k], c[j + 1 + k], I);
            d[j] = __fmul_rn(oma, I);
        }

        float4 v4, z4, s4, l4;
        float* v4p = &v4.x; float* z4p = &z4.x; float* s4p = &s4.x; float* l4p = &l4.x;

        #pragma unroll
        for (int j = 0; j < 4; j++) {
            const float fmares = __fmaf_rn(alpha, vp, d[j]);
            vp = spike ? d[j] : fmares;          // 8-cycle chain: FMA || FSETP -> FSEL
            const bool  sp_new = (vp >= THRV);
            const float z = __fmul_rn(BETA, __fadd_rn(vp, -THRV));   // matches ref op order
            v4p[j] = vp;                         // v history = pre-reset potential
            z4p[j] = z;
            s4p[j] = sp_new ? 1.0f : 0.0f;
            spike  = sp_new;

            // warp max over 32 filters via monotone uint key + REDUX
            unsigned bits = __float_as_uint(z);
            unsigned key  = ((int)bits < 0) ? ~bits : (bits | 0x80000000u);
            unsigned kmax = __reduce_max_sync(0xffffffffu, key);
            unsigned rb   = (kmax & 0x80000000u) ? (kmax ^ 0x80000000u) : ~kmax;
            l4p[j] = __uint_as_float(rb);
        }

        *(float4*)(vout + g) = v4;
        *(float4*)(zout + g) = z4;
        *(float4*)(souT + g) = s4;
        if (lane == 0) *(float4*)(lout + g) = l4;

        #pragma unroll
        for (int k = 0; k < 8; k++) hist[k] = c[k + 4];
    }
}

extern "C" void kernel_launch(void* const* d_in, const int* in_sizes, int n_in,
                              void* d_out, int out_size)
{
    const float* x  = (const float*)d_in[0];
    const float* wa = (const float*)d_in[1];
    const float* wb = (const float*)d_in[2];
    const float* ta = (const float*)d_in[3];
    const float* tb = (const float*)d_in[4];
    float* out = (float*)d_out;

    // 8192 warps total: one per (b, chunk); 4 warps/block -> 2048 blocks
    const int total_warps = BSZ * NCHUNK;
    const int threads = 128;
    const int blocks  = (total_warps * 32) / threads;
    snn_scan_kernel<<<blocks, threads>>>(x, wa, wb, ta, tb, out);
}

// round 3
// speedup vs baseline: 4.1570x; 4.1570x over previous
#include <cuda_runtime.h>
#include <math.h>

#define BSZ     64
#define NF      16
#define NFILT   32
#define KTAP    8
#define LSEQ    16384
#define THRV    0.25f
#define BETA    15.0f
#define TCH     256         // chunk length
#define WUP     64          // warm-up: alpha^64 ~ 5e-10 (validated R1/R2)
#define NCHUNK  (LSEQ / TCH)
#define TBUF    16          // timesteps buffered before coalesced flush
#define PITCH   17          // odd pitch -> conflict-free STS
#define WPB     2           // warps per block

// one warp per (b, chunk); lane = filter index 0..31
__global__ __launch_bounds__(WPB * 32, 16)
void snn_scan_kernel(const float* __restrict__ x,
                     const float* __restrict__ wa,
                     const float* __restrict__ wb,
                     const float* __restrict__ ta,
                     const float* __restrict__ tb,
                     float* __restrict__ out)
{
    __shared__ float2 buf[WPB][NFILT][PITCH];   // {v_pre, z} per (f, t mod 16)

    const int warp_global = (blockIdx.x * blockDim.x + threadIdx.x) >> 5;
    const int w    = (threadIdx.x >> 5);
    const int lane = threadIdx.x & 31;
    if (warp_global >= BSZ * NCHUNK) return;

    const int b     = warp_global / NCHUNK;
    const int chunk = warp_global % NCHUNK;
    const int f     = lane;
    const int ch    = f >> 4;

    // ---- per-filter constants ----
    const float* wsrc = (ch == 0) ? (wa + f * KTAP) : (wb + (f - NF) * KTAP);
    float wgt[KTAP];
    float ss = 0.f;
    #pragma unroll
    for (int k = 0; k < KTAP; k++) { wgt[k] = wsrc[k]; ss = __fmaf_rn(wgt[k], wgt[k], ss); }
    const float inv = 1.0f / fmaxf(sqrtf(ss), 1e-8f);
    #pragma unroll
    for (int k = 0; k < KTAP; k++) wgt[k] = __fmul_rn(wgt[k], inv);

    const float raw   = (ch == 0) ? ta[f] : tb[f - NF];
    const float sp    = fmaxf(raw, 0.f) + log1pf(expf(-fabsf(raw)));   // softplus
    const float tau   = sp + 1e-4f;
    const float alpha = expf(-1.0f / tau);
    const float oma   = 1.0f - alpha;

    const float* xb = x + (size_t)(b * 2 + ch) * LSEQ;

    const int t0   = chunk * TCH;
    const int wlen = (chunk == 0) ? 0 : WUP;
    const int ts   = t0 - wlen;

    // ---- conv history window: hist[i] = x[tcur-8+i] ----
    float hist[8];
    if (chunk == 0) {
        #pragma unroll
        for (int k = 0; k < 8; k++) hist[k] = 0.f;
    } else {
        const float4 h0 = *(const float4*)(xb + ts - 8);
        const float4 h1 = *(const float4*)(xb + ts - 4);
        hist[0]=h0.x; hist[1]=h0.y; hist[2]=h0.z; hist[3]=h0.w;
        hist[4]=h1.x; hist[5]=h1.y; hist[6]=h1.z; hist[7]=h1.w;
    }

    // vp-form recurrence (exact): vp_t = spike_{t-1} ? d_t : fma(alpha, vp_{t-1}, d_t)
    float vp = 0.f;
    bool  spike = false;

    // ---- phase 1: warm-up (no outputs) ----
    for (int g = 0; g < wlen; g += 4) {
        const float4 c4 = *(const float4*)(xb + ts + g);
        float c[12];
        #pragma unroll
        for (int k = 0; k < 8; k++) c[k] = hist[k];
        c[8]=c4.x; c[9]=c4.y; c[10]=c4.z; c[11]=c4.w;
        float d[4];
        #pragma unroll
        for (int j = 0; j < 4; j++) {
            float I = 0.f;
            #pragma unroll
            for (int k = 0; k < 8; k++) I = __fmaf_rn(wgt[k], c[j + 1 + k], I);
            d[j] = __fmul_rn(oma, I);
        }
        #pragma unroll
        for (int j = 0; j < 4; j++) {
            const float fmares = __fmaf_rn(alpha, vp, d[j]);
            vp    = spike ? d[j] : fmares;
            spike = (vp >= THRV);
        }
        #pragma unroll
        for (int k = 0; k < 8; k++) hist[k] = c[k + 4];
    }

    const size_t plane = (size_t)BSZ * NFILT * LSEQ;
    const size_t bbase = (size_t)b * NFILT * LSEQ;

    // ---- phase 2: main scan, buffered + coalesced flush every TBUF steps ----
    for (int tile = 0; tile < TCH / TBUF; ++tile) {
        const int tbase = t0 + tile * TBUF;

        #pragma unroll
        for (int g = 0; g < TBUF; g += 4) {
            const float4 c4 = *(const float4*)(xb + tbase + g);
            float c[12];
            #pragma unroll
            for (int k = 0; k < 8; k++) c[k] = hist[k];
            c[8]=c4.x; c[9]=c4.y; c[10]=c4.z; c[11]=c4.w;

            float d[4];
            #pragma unroll
            for (int j = 0; j < 4; j++) {
                float I = 0.f;
                #pragma unroll
                for (int k = 0; k < 8; k++) I = __fmaf_rn(wgt[k], c[j + 1 + k], I);
                d[j] = __fmul_rn(oma, I);
            }

            #pragma unroll
            for (int j = 0; j < 4; j++) {
                const float fmares = __fmaf_rn(alpha, vp, d[j]);
                vp = spike ? d[j] : fmares;
                spike = (vp >= THRV);
                const float z = __fmul_rn(BETA, __fadd_rn(vp, -THRV));
                buf[w][lane][g + j] = make_float2(vp, z);   // conflict-free STS.64
            }
            #pragma unroll
            for (int k = 0; k < 8; k++) hist[k] = c[k + 4];
        }

        __syncwarp();

        // ---- coalesced flush: lane -> (filter = rb + lane/4, t4 = 4*(lane%4)) ----
        {
            const int r4 = lane >> 2;
            const int c4i = (lane & 3) << 2;
            #pragma unroll
            for (int rb = 0; rb < NFILT; rb += 8) {
                const int ff = rb + r4;
                const float2 p0 = buf[w][ff][c4i + 0];
                const float2 p1 = buf[w][ff][c4i + 1];
                const float2 p2 = buf[w][ff][c4i + 2];
                const float2 p3 = buf[w][ff][c4i + 3];
                const float4 v4 = make_float4(p0.x, p1.x, p2.x, p3.x);
                const float4 z4 = make_float4(p0.y, p1.y, p2.y, p3.y);
                const float4 s4 = make_float4(z4.x >= 0.f ? 1.f : 0.f,
                                              z4.y >= 0.f ? 1.f : 0.f,
                                              z4.z >= 0.f ? 1.f : 0.f,
                                              z4.w >= 0.f ? 1.f : 0.f);
                const size_t off = bbase + (size_t)ff * LSEQ + tbase + c4i;
                *(float4*)(out + off)             = v4;
                *(float4*)(out + plane + off)     = z4;
                *(float4*)(out + 2 * plane + off) = s4;
            }

            // logits: column max over 32 filters, split halves across lane groups
            const int tt = lane & 15;
            const int fh = (lane >> 4) << 4;
            float m = buf[w][fh][tt].y;
            #pragma unroll
            for (int i = 1; i < 16; i++)
                m = fmaxf(m, buf[w][fh + i][tt].y);
            const float o = __shfl_down_sync(0xffffffffu, m, 16);
            if (lane < 16)
                out[3 * plane + (size_t)b * LSEQ + tbase + tt] = fmaxf(m, o);
        }

        __syncwarp();
    }
}

extern "C" void kernel_launch(void* const* d_in, const int* in_sizes, int n_in,
                              void* d_out, int out_size)
{
    const float* x  = (const float*)d_in[0];
    const float* wa = (const float*)d_in[1];
    const float* wb = (const float*)d_in[2];
    const float* ta = (const float*)d_in[3];
    const float* tb = (const float*)d_in[4];
    float* out = (float*)d_out;

    // 4096 warps: one per (b, chunk); 2 warps/block -> 2048 blocks
    const int total_warps = BSZ * NCHUNK;
    const int threads = WPB * 32;
    const int blocks  = (total_warps * 32) / threads;
    snn_scan_kernel<<<blocks, threads>>>(x, wa, wb, ta, tb, out);
}

// round 4
// speedup vs baseline: 5.9957x; 1.4423x over previous
#include <cuda_runtime.h>
#include <math.h>

#define BSZ     64
#define NF      16
#define NFILT   32
#define KTAP    8
#define LSEQ    16384
#define THRV    0.25f
#define BETA    15.0f
#define TCH     128         // chunk length (stores now amplification-free)
#define WUP     64          // warm-up: alpha^64 ~ 5e-10 (validated R1-R3)
#define NCHUNK  (LSEQ / TCH)
#define TBUF    16          // timesteps buffered before coalesced flush
#define PITCH   17          // odd pitch -> conflict-light smem
#define WPB     4           // warps per block

// one warp per (b, chunk); lane = filter index 0..31
__global__ __launch_bounds__(WPB * 32, 8)
void snn_scan_kernel(const float* __restrict__ x,
                     const float* __restrict__ wa,
                     const float* __restrict__ wb,
                     const float* __restrict__ ta,
                     const float* __restrict__ tb,
                     float* __restrict__ out)
{
    __shared__ float buf[WPB][NFILT][PITCH];   // v_pre per (f, t mod 16)

    const int warp_global = (blockIdx.x * blockDim.x + threadIdx.x) >> 5;
    const int w    = (threadIdx.x >> 5);
    const int lane = threadIdx.x & 31;
    if (warp_global >= BSZ * NCHUNK) return;

    const int b     = warp_global / NCHUNK;
    const int chunk = warp_global % NCHUNK;
    const int f     = lane;
    const int ch    = f >> 4;

    // ---- per-filter constants ----
    const float* wsrc = (ch == 0) ? (wa + f * KTAP) : (wb + (f - NF) * KTAP);
    float wgt[KTAP];
    float ss = 0.f;
    #pragma unroll
    for (int k = 0; k < KTAP; k++) { wgt[k] = wsrc[k]; ss = __fmaf_rn(wgt[k], wgt[k], ss); }
    const float inv = 1.0f / fmaxf(sqrtf(ss), 1e-8f);
    #pragma unroll
    for (int k = 0; k < KTAP; k++) wgt[k] = __fmul_rn(wgt[k], inv);

    const float raw   = (ch == 0) ? ta[f] : tb[f - NF];
    const float sp    = fmaxf(raw, 0.f) + log1pf(expf(-fabsf(raw)));   // softplus
    const float tau   = sp + 1e-4f;
    const float alpha = expf(-1.0f / tau);
    const float oma   = 1.0f - alpha;

    const float* xb = x + (size_t)(b * 2 + ch) * LSEQ;

    const int t0   = chunk * TCH;
    const int wlen = (chunk == 0) ? 0 : WUP;
    const int ts   = t0 - wlen;

    // ---- conv history window: hist[i] = x[tcur-8+i] ----
    float hist[8];
    if (chunk == 0) {
        #pragma unroll
        for (int k = 0; k < 8; k++) hist[k] = 0.f;
    } else {
        const float4 h0 = *(const float4*)(xb + ts - 8);
        const float4 h1 = *(const float4*)(xb + ts - 4);
        hist[0]=h0.x; hist[1]=h0.y; hist[2]=h0.z; hist[3]=h0.w;
        hist[4]=h1.x; hist[5]=h1.y; hist[6]=h1.z; hist[7]=h1.w;
    }

    // vp-form recurrence (exact): vp_t = spike_{t-1} ? d_t : fma(alpha, vp_{t-1}, d_t)
    float vp = 0.f;
    bool  spike = false;

    // ---- phase 1: warm-up (no outputs) ----
    for (int g = 0; g < wlen; g += 4) {
        const float4 c4 = *(const float4*)(xb + ts + g);
        float c[12];
        #pragma unroll
        for (int k = 0; k < 8; k++) c[k] = hist[k];
        c[8]=c4.x; c[9]=c4.y; c[10]=c4.z; c[11]=c4.w;
        float d[4];
        #pragma unroll
        for (int j = 0; j < 4; j++) {
            float I = 0.f;
            #pragma unroll
            for (int k = 0; k < 8; k++) I = __fmaf_rn(wgt[k], c[j + 1 + k], I);
            d[j] = __fmul_rn(oma, I);
        }
        #pragma unroll
        for (int j = 0; j < 4; j++) {
            const float fmares = __fmaf_rn(alpha, vp, d[j]);
            vp    = spike ? d[j] : fmares;
            spike = (vp >= THRV);
        }
        #pragma unroll
        for (int k = 0; k < 8; k++) hist[k] = c[k + 4];
    }

    const size_t plane = (size_t)BSZ * NFILT * LSEQ;
    const size_t bbase = (size_t)b * NFILT * LSEQ;

    // ---- phase 2: main scan, buffered + coalesced flush every TBUF steps ----
    for (int tile = 0; tile < TCH / TBUF; ++tile) {
        const int tbase = t0 + tile * TBUF;

        #pragma unroll
        for (int g = 0; g < TBUF; g += 4) {
            const float4 c4 = *(const float4*)(xb + tbase + g);
            float c[12];
            #pragma unroll
            for (int k = 0; k < 8; k++) c[k] = hist[k];
            c[8]=c4.x; c[9]=c4.y; c[10]=c4.z; c[11]=c4.w;

            float d[4];
            #pragma unroll
            for (int j = 0; j < 4; j++) {
                float I = 0.f;
                #pragma unroll
                for (int k = 0; k < 8; k++) I = __fmaf_rn(wgt[k], c[j + 1 + k], I);
                d[j] = __fmul_rn(oma, I);
            }

            #pragma unroll
            for (int j = 0; j < 4; j++) {
                const float fmares = __fmaf_rn(alpha, vp, d[j]);
                vp = spike ? d[j] : fmares;
                spike = (vp >= THRV);
                buf[w][lane][g + j] = vp;          // STS.32, conflict-free
            }
            #pragma unroll
            for (int k = 0; k < 8; k++) hist[k] = c[k + 4];
        }

        __syncwarp();

        // ---- coalesced flush: lane -> (filter = rb + lane/4, t4 = 4*(lane%4)) ----
        {
            const int r4  = lane >> 2;
            const int c4i = (lane & 3) << 2;
            #pragma unroll
            for (int rb = 0; rb < NFILT; rb += 8) {
                const int ff = rb + r4;
                const float4 v4 = make_float4(buf[w][ff][c4i + 0],
                                              buf[w][ff][c4i + 1],
                                              buf[w][ff][c4i + 2],
                                              buf[w][ff][c4i + 3]);
                // z = BETA*(vp - THR), s = (vp >= THR)  — exact recompute
                const float4 z4 = make_float4(__fmul_rn(BETA, __fadd_rn(v4.x, -THRV)),
                                              __fmul_rn(BETA, __fadd_rn(v4.y, -THRV)),
                                              __fmul_rn(BETA, __fadd_rn(v4.z, -THRV)),
                                              __fmul_rn(BETA, __fadd_rn(v4.w, -THRV)));
                const float4 s4 = make_float4(v4.x >= THRV ? 1.f : 0.f,
                                              v4.y >= THRV ? 1.f : 0.f,
                                              v4.z >= THRV ? 1.f : 0.f,
                                              v4.w >= THRV ? 1.f : 0.f);
                const size_t off = bbase + (size_t)ff * LSEQ + tbase + c4i;
                *(float4*)(out + off)             = v4;
                *(float4*)(out + plane + off)     = z4;
                *(float4*)(out + 2 * plane + off) = s4;
            }

            // logits: max_f z == z(max_f vp) exactly (z monotone under RN)
            const int tt = lane & 15;
            const int fh = (lane >> 4) << 4;
            float m = buf[w][fh][tt];
            #pragma unroll
            for (int i = 1; i < 16; i++)
                m = fmaxf(m, buf[w][fh + i][tt]);
            const float o = __shfl_down_sync(0xffffffffu, m, 16);
            if (lane < 16) {
                const float vmax = fmaxf(m, o);
                out[3 * plane + (size_t)b * LSEQ + tbase + tt] =
                    __fmul_rn(BETA, __fadd_rn(vmax, -THRV));
            }
        }

        __syncwarp();
    }
}

extern "C" void kernel_launch(void* const* d_in, const int* in_sizes, int n_in,
                              void* d_out, int out_size)
{
    const float* x  = (const float*)d_in[0];
    const float* wa = (const float*)d_in[1];
    const float* wb = (const float*)d_in[2];
    const float* ta = (const float*)d_in[3];
    const float* tb = (const float*)d_in[4];
    float* out = (float*)d_out;

    // 8192 warps: one per (b, chunk); 4 warps/block -> 2048 blocks
    const int total_warps = BSZ * NCHUNK;
    const int threads = WPB * 32;
    const int blocks  = (total_warps * 32) / threads;
    snn_scan_kernel<<<blocks, threads>>>(x, wa, wb, ta, tb, out);
}

// round 5
// speedup vs baseline: 6.5866x; 1.0985x over previous
#include <cuda_runtime.h>
#include <math.h>

#define BSZ     64
#define NF      16
#define NFILT   32
#define KTAP    8
#define LSEQ    16384
#define THRV    0.25f
#define BETA    15.0f
#define TCH     128         // chunk length
#define WUP     64          // warm-up: alpha^64 ~ 5e-10 (validated R1-R4)
#define NCHUNK  (LSEQ / TCH)
#define TBUF    32          // timesteps buffered -> full 128B lines per flush
#define PITCH   33          // odd pitch: STS & LDS conflict-free (see analysis)
#define WPB     4           // warps per block

// one warp per (b, chunk); lane = filter index 0..31
__global__ __launch_bounds__(WPB * 32, 10)
void snn_scan_kernel(const float* __restrict__ x,
                     const float* __restrict__ wa,
                     const float* __restrict__ wb,
                     const float* __restrict__ ta,
                     const float* __restrict__ tb,
                     float* __restrict__ out)
{
    __shared__ float buf[WPB][NFILT][PITCH];   // v_pre per (f, t mod 32)

    const int warp_global = (blockIdx.x * blockDim.x + threadIdx.x) >> 5;
    const int w    = (threadIdx.x >> 5);
    const int lane = threadIdx.x & 31;
    if (warp_global >= BSZ * NCHUNK) return;

    const int b     = warp_global / NCHUNK;
    const int chunk = warp_global % NCHUNK;
    const int f     = lane;
    const int ch    = f >> 4;

    // ---- per-filter constants ----
    const float* wsrc = (ch == 0) ? (wa + f * KTAP) : (wb + (f - NF) * KTAP);
    float wgt[KTAP];
    float ss = 0.f;
    #pragma unroll
    for (int k = 0; k < KTAP; k++) { wgt[k] = wsrc[k]; ss = __fmaf_rn(wgt[k], wgt[k], ss); }
    const float inv = 1.0f / fmaxf(sqrtf(ss), 1e-8f);
    #pragma unroll
    for (int k = 0; k < KTAP; k++) wgt[k] = __fmul_rn(wgt[k], inv);

    const float raw   = (ch == 0) ? ta[f] : tb[f - NF];
    const float sp    = fmaxf(raw, 0.f) + log1pf(expf(-fabsf(raw)));   // softplus
    const float tau   = sp + 1e-4f;
    const float alpha = expf(-1.0f / tau);
    const float oma   = 1.0f - alpha;

    const float* xb = x + (size_t)(b * 2 + ch) * LSEQ;

    const int t0   = chunk * TCH;
    const int wlen = (chunk == 0) ? 0 : WUP;
    const int ts   = t0 - wlen;

    // ---- conv history window: hist[i] = x[tcur-8+i] ----
    float hist[8];
    if (chunk == 0) {
        #pragma unroll
        for (int k = 0; k < 8; k++) hist[k] = 0.f;
    } else {
        const float4 h0 = *(const float4*)(xb + ts - 8);
        const float4 h1 = *(const float4*)(xb + ts - 4);
        hist[0]=h0.x; hist[1]=h0.y; hist[2]=h0.z; hist[3]=h0.w;
        hist[4]=h1.x; hist[5]=h1.y; hist[6]=h1.z; hist[7]=h1.w;
    }

    // vp-form recurrence (exact): vp_t = spike_{t-1} ? d_t : fma(alpha, vp_{t-1}, d_t)
    float vp = 0.f;
    bool  spike = false;

    // ---- phase 1: warm-up (no outputs) ----
    for (int g = 0; g < wlen; g += 4) {
        const float4 c4 = *(const float4*)(xb + ts + g);
        float c[12];
        #pragma unroll
        for (int k = 0; k < 8; k++) c[k] = hist[k];
        c[8]=c4.x; c[9]=c4.y; c[10]=c4.z; c[11]=c4.w;
        float d[4];
        #pragma unroll
        for (int j = 0; j < 4; j++) {
            float I = 0.f;
            #pragma unroll
            for (int k = 0; k < 8; k++) I = __fmaf_rn(wgt[k], c[j + 1 + k], I);
            d[j] = __fmul_rn(oma, I);
        }
        #pragma unroll
        for (int j = 0; j < 4; j++) {
            const float fmares = __fmaf_rn(alpha, vp, d[j]);
            vp    = spike ? d[j] : fmares;
            spike = (vp >= THRV);
        }
        #pragma unroll
        for (int k = 0; k < 8; k++) hist[k] = c[k + 4];
    }

    const size_t plane = (size_t)BSZ * NFILT * LSEQ;
    const size_t bbase = (size_t)b * NFILT * LSEQ;

    // ---- phase 2: main scan, buffered + whole-line coalesced flush ----
    for (int tile = 0; tile < TCH / TBUF; ++tile) {
        const int tbase = t0 + tile * TBUF;

        #pragma unroll
        for (int g = 0; g < TBUF; g += 4) {
            const float4 c4 = *(const float4*)(xb + tbase + g);
            float c[12];
            #pragma unroll
            for (int k = 0; k < 8; k++) c[k] = hist[k];
            c[8]=c4.x; c[9]=c4.y; c[10]=c4.z; c[11]=c4.w;

            float d[4];
            #pragma unroll
            for (int j = 0; j < 4; j++) {
                float I = 0.f;
                #pragma unroll
                for (int k = 0; k < 8; k++) I = __fmaf_rn(wgt[k], c[j + 1 + k], I);
                d[j] = __fmul_rn(oma, I);
            }

            #pragma unroll
            for (int j = 0; j < 4; j++) {
                const float fmares = __fmaf_rn(alpha, vp, d[j]);
                vp = spike ? d[j] : fmares;
                spike = (vp >= THRV);
                buf[w][lane][g + j] = vp;          // STS.32: (lane+t)%32 -> conflict-free
            }
            #pragma unroll
            for (int k = 0; k < 8; k++) hist[k] = c[k + 4];
        }

        __syncwarp();

        // ---- flush: 4 filters x 128B per STG.128, whole lines -> streaming ok ----
        {
            const int fr   = lane >> 3;            // 0..3: filter within group
            const int tseg = (lane & 7) << 2;      // 0,4,...,28: 16B segment
            #pragma unroll
            for (int rb = 0; rb < NFILT; rb += 4) {
                const int ff = rb + fr;
                const float v0 = buf[w][ff][tseg + 0];
                const float v1 = buf[w][ff][tseg + 1];
                const float v2 = buf[w][ff][tseg + 2];
                const float v3 = buf[w][ff][tseg + 3];
                const float4 v4 = make_float4(v0, v1, v2, v3);
                const float4 z4 = make_float4(__fmul_rn(BETA, __fadd_rn(v0, -THRV)),
                                              __fmul_rn(BETA, __fadd_rn(v1, -THRV)),
                                              __fmul_rn(BETA, __fadd_rn(v2, -THRV)),
                                              __fmul_rn(BETA, __fadd_rn(v3, -THRV)));
                const float4 s4 = make_float4(v0 >= THRV ? 1.f : 0.f,
                                              v1 >= THRV ? 1.f : 0.f,
                                              v2 >= THRV ? 1.f : 0.f,
                                              v3 >= THRV ? 1.f : 0.f);
                float* p = out + (bbase + (size_t)ff * LSEQ + tbase + tseg);
                __stcs((float4*)p, v4);
                __stcs((float4*)(p + plane), z4);
                __stcs((float4*)(p + 2 * plane), s4);
            }

            // logits: lane = t; tree max over 32 filters (conflict-free LDS)
            float m0 = buf[w][0][lane], m1 = buf[w][1][lane];
            float m2 = buf[w][2][lane], m3 = buf[w][3][lane];
            #pragma unroll
            for (int i = 4; i < NFILT; i += 4) {
                m0 = fmaxf(m0, buf[w][i + 0][lane]);
                m1 = fmaxf(m1, buf[w][i + 1][lane]);
                m2 = fmaxf(m2, buf[w][i + 2][lane]);
                m3 = fmaxf(m3, buf[w][i + 3][lane]);
            }
            const float vmax = fmaxf(fmaxf(m0, m1), fmaxf(m2, m3));
            // max_f z == z(max_f vp) exactly (z monotone under RN)
            __stcs(out + 3 * plane + (size_t)b * LSEQ + tbase + lane,
                   __fmul_rn(BETA, __fadd_rn(vmax, -THRV)));
        }

        __syncwarp();
    }
}

extern "C" void kernel_launch(void* const* d_in, const int* in_sizes, int n_in,
                              void* d_out, int out_size)
{
    const float* x  = (const float*)d_in[0];
    const float* wa = (const float*)d_in[1];
    const float* wb = (const float*)d_in[2];
    const float* ta = (const float*)d_in[3];
    const float* tb = (const float*)d_in[4];
    float* out = (float*)d_out;

    // 8192 warps: one per (b, chunk); 4 warps/block -> 2048 blocks
    const int total_warps = BSZ * NCHUNK;
    const int threads = WPB * 32;
    const int blocks  = (total_warps * 32) / threads;
    snn_scan_kernel<<<blocks, threads>>>(x, wa, wb, ta, tb, out);
}